// round 2
// baseline (speedup 1.0000x reference)
#include <cuda_runtime.h>

// BilinearResNet fused, GB300 sm_103a — round 2
// f32x2 FMA, 4 rows x 4 cols per thread, W reordered+L1-resident,
// KC=16 triple-buffered cp.async, 2 CTAs/SM.

#define IN_DIM 784
#define DM     16
#define HID    6
#define NB     4
#define NC     10
#define ROWS   256
#define NTH    256
#define KC     16          // floats of k per chunk (64B, sector aligned)
#define NCHUNK 49          // 784/16
#define NKQ    4           // float4 groups per chunk
#define XPAD   20          // row stride in smem (20 mod 32 -> conflict-free)
#define XSBUF  (ROWS*XPAD) // 5120 floats per buffer

// smem float offsets
#define XS0   0
#define LWo   (3*XSBUF)              // 15360
#define RWo   (LWo + NB*HID*DM)      // +384
#define DTo   (RWo + NB*HID*DM)      // +384 (D transposed [i][a][j])
#define WHo   (DTo + NB*DM*HID)      // +384
#define SMEM_FLOATS (WHo + NC*DM)    // +160 = 16672 floats = 66,688 B
#define HXS   0                      // aliases x buffers after mainloop (256*17=4352 < 15360)

// Reordered embed weight: Wq[kq][j][k4], kq = k>>2, 16B per (kq,j)
__device__ __align__(16) float g_Wq[DM * IN_DIM];

__global__ void reorder_W_kernel(const float* __restrict__ We) {
    int idx = blockIdx.x * NTH + threadIdx.x;
    if (idx < DM * IN_DIM) {
        int j = idx / IN_DIM;
        int k = idx - j * IN_DIM;
        g_Wq[(k >> 2) * (DM * 4) + j * 4 + (k & 3)] = We[idx];
    }
}

__device__ __forceinline__ void cp16(unsigned dst, const void* src) {
    asm volatile("cp.async.cg.shared.global [%0], [%1], 16;\n" :: "r"(dst), "l"(src));
}
__device__ __forceinline__ void fma2(unsigned long long& acc,
                                     unsigned long long a, unsigned long long b) {
    asm("fma.rn.f32x2 %0, %1, %2, %0;" : "+l"(acc) : "l"(a), "l"(b));
}

__global__ __launch_bounds__(NTH, 2)
void bilinear_resnet_kernel(const float* __restrict__ x,
                            const float* __restrict__ Lw,
                            const float* __restrict__ Rw,
                            const float* __restrict__ Dw,
                            const float* __restrict__ Wh,
                            float* __restrict__ out,
                            int batch)
{
    extern __shared__ float sm[];
    const int tid  = threadIdx.x;
    const int warp = tid >> 5;
    const int lane = tid & 31;
    const int rs   = lane >> 2;   // 0..7 row-set within warp
    const int cg   = lane & 3;    // 0..3 col group (cols cg, cg+4, cg+8, cg+12)

    // stage small block weights
    for (int i = tid; i < NB*HID*DM; i += NTH) { sm[LWo+i] = Lw[i]; sm[RWo+i] = Rw[i]; }
    for (int idx = tid; idx < NB*DM*HID; idx += NTH) {
        int i = idx / (DM*HID); int r = idx % (DM*HID);
        int j = r / HID; int a = r % HID;
        sm[DTo + i*(DM*HID) + a*DM + j] = Dw[idx];   // transpose to [i][a][j]
    }
    for (int i = tid; i < NC*DM; i += NTH) sm[WHo+i] = Wh[i];

    const long long row0 = (long long)blockIdx.x * ROWS;
    const unsigned smbase = (unsigned)__cvta_generic_to_shared(sm);

    // thread tid stages row tid of each chunk: 4 x 16B
    const float* xrow = x + (row0 + tid) * (long long)IN_DIM;
    auto stage = [&](int c, int buf) {
        const float* src = xrow + c * KC;
        unsigned dst = smbase + (unsigned)((buf * XSBUF + tid * XPAD) * 4);
        #pragma unroll
        for (int v = 0; v < 4; v++) cp16(dst + v * 16, src + v * 4);
        asm volatile("cp.async.commit_group;\n" ::: "memory");
    };

    stage(0, 0);
    stage(1, 1);

    // per-thread row offsets in x buffer (rows warp*32 + rs + 8i)
    int ro[4];
    #pragma unroll
    for (int i = 0; i < 4; i++) ro[i] = (warp * 32 + rs + 8 * i) * XPAD;

    unsigned long long acc[4][4];
    #pragma unroll
    for (int i = 0; i < 4; i++)
        #pragma unroll
        for (int jj = 0; jj < 4; jj++) acc[i][jj] = 0ull;

    for (int c = 0; c < NCHUNK; c++) {
        if (c < NCHUNK - 1) asm volatile("cp.async.wait_group 1;\n" ::: "memory");
        else                asm volatile("cp.async.wait_group 0;\n" ::: "memory");
        __syncthreads();
        if (c + 2 < NCHUNK) stage(c + 2, (c + 2) % 3);

        const float* xb = sm + ((c % 3) * XSBUF);
        #pragma unroll
        for (int kq = 0; kq < NKQ; kq++) {
            const int kqg = c * NKQ + kq;
            ulonglong2 wv[4];
            #pragma unroll
            for (int jj = 0; jj < 4; jj++)
                wv[jj] = *(const ulonglong2*)&g_Wq[kqg * (DM*4) + (cg + 4*jj) * 4];
            ulonglong2 xv[4];
            #pragma unroll
            for (int i = 0; i < 4; i++)
                xv[i] = *(const ulonglong2*)(xb + ro[i] + kq * 4);
            #pragma unroll
            for (int i = 0; i < 4; i++)
                #pragma unroll
                for (int jj = 0; jj < 4; jj++) {
                    fma2(acc[i][jj], xv[i].x, wv[jj].x);
                    fma2(acc[i][jj], xv[i].y, wv[jj].y);
                }
        }
    }

    // write h_x tile (aliases x buffers — must sync first)
    __syncthreads();
    #pragma unroll
    for (int i = 0; i < 4; i++) {
        int row = warp * 32 + rs + 8 * i;
        #pragma unroll
        for (int jj = 0; jj < 4; jj++) {
            unsigned long long a = acc[i][jj];
            float v = __uint_as_float((unsigned)a) + __uint_as_float((unsigned)(a >> 32));
            sm[HXS + row * 17 + (cg + 4 * jj)] = v;
        }
    }
    __syncthreads();

    // ---- phase 2: one row per thread (256 rows, 256 threads) ----
    {
        float hx[DM];
        #pragma unroll
        for (int j = 0; j < DM; j++) hx[j] = sm[HXS + tid * 17 + j];

        const long long grow  = row0 + tid;
        const long long hbase = (long long)batch * NC;
        const long long hblk  = (long long)batch * HID;

        #pragma unroll
        for (int ib = 0; ib < NB; ib++) {
            float h[HID];
            #pragma unroll
            for (int a = 0; a < HID; a++) {
                const float4* lp = (const float4*)(sm + LWo + ib*(HID*DM) + a*DM);
                const float4* rp = (const float4*)(sm + RWo + ib*(HID*DM) + a*DM);
                float su = 0.f, sv = 0.f;
                #pragma unroll
                for (int q = 0; q < 4; q++) {
                    float4 l4 = lp[q], r4 = rp[q];
                    su = fmaf(l4.x, hx[q*4+0], fmaf(l4.y, hx[q*4+1],
                         fmaf(l4.z, hx[q*4+2], fmaf(l4.w, hx[q*4+3], su))));
                    sv = fmaf(r4.x, hx[q*4+0], fmaf(r4.y, hx[q*4+1],
                         fmaf(r4.z, hx[q*4+2], fmaf(r4.w, hx[q*4+3], sv))));
                }
                h[a] = su * sv;
            }
            #pragma unroll
            for (int a = 0; a < HID; a++)
                out[hbase + (long long)ib*hblk + grow*HID + a] = h[a];
            #pragma unroll
            for (int a = 0; a < HID; a++) {
                const float4* dp = (const float4*)(sm + DTo + ib*(DM*HID) + a*DM);
                #pragma unroll
                for (int q = 0; q < 4; q++) {
                    float4 d4 = dp[q];
                    hx[q*4+0] = fmaf(h[a], d4.x, hx[q*4+0]);
                    hx[q*4+1] = fmaf(h[a], d4.y, hx[q*4+1]);
                    hx[q*4+2] = fmaf(h[a], d4.z, hx[q*4+2]);
                    hx[q*4+3] = fmaf(h[a], d4.w, hx[q*4+3]);
                }
            }
        }

        #pragma unroll
        for (int cc = 0; cc < NC; cc++) {
            const float4* wp = (const float4*)(sm + WHo + cc*DM);
            float s = 0.f;
            #pragma unroll
            for (int q = 0; q < 4; q++) {
                float4 w4 = wp[q];
                s = fmaf(w4.x, hx[q*4+0], fmaf(w4.y, hx[q*4+1],
                    fmaf(w4.z, hx[q*4+2], fmaf(w4.w, hx[q*4+3], s))));
            }
            out[grow*NC + cc] = s;
        }
    }
}

extern "C" void kernel_launch(void* const* d_in, const int* in_sizes, int n_in,
                              void* d_out, int out_size)
{
    const float* x  = (const float*)d_in[0];
    const float* We = (const float*)d_in[1];
    const float* Lw = (const float*)d_in[2];
    const float* Rw = (const float*)d_in[3];
    const float* Dw = (const float*)d_in[4];
    const float* Wh = (const float*)d_in[5];
    float* out = (float*)d_out;

    int batch = in_sizes[0] / IN_DIM;              // 65536
    int grid  = batch / ROWS;                      // 256

    reorder_W_kernel<<<(DM*IN_DIM + NTH - 1)/NTH, NTH>>>(We);

    size_t smem = (size_t)SMEM_FLOATS * sizeof(float);   // ~66.7 KB
    cudaFuncSetAttribute(bilinear_resnet_kernel,
                         cudaFuncAttributeMaxDynamicSharedMemorySize, (int)smem);
    bilinear_resnet_kernel<<<grid, NTH, smem>>>(x, Lw, Rw, Dw, Wh, out, batch);
}

// round 4
// speedup vs baseline: 1.1370x; 1.1370x over previous
#include <cuda_runtime.h>
#include <cuda.h>

// BilinearResNet fused, GB300 sm_103a — round 4 (round-3 kernel, compile fix)
// TMA double-buffered x staging (kills LDGSTS issue bottleneck),
// f32x2 FMA, 2 rows/thread, W smem broadcast, phase2 in registers.

#define IN_DIM 784
#define DM     16
#define HID    6
#define NB     4
#define NC     10
#define KC     28            // floats per k-chunk (112B rows in smem)
#define NCHUNK 28            // 784 / 28
#define NKQ    7             // float4 groups per chunk
#define TROWS  256           // rows per CTA tile
#define NTH    128
#define RPT    2             // rows per thread

// smem float offsets
#define XBUF   (TROWS*KC)        // 7168 floats per buffer
#define WOFF   (2*XBUF)          // 14336
#define WSZ    (DM*IN_DIM)       // 12544
#define MBAR_F (WOFF+WSZ)        // 26880 (byte 107520, 16B aligned)
#define SMEM_FLOATS (MBAR_F + 8)

// reordered weights in global (written by pre-kernel)
__device__ __align__(16) float g_Wq[DM * IN_DIM];     // [kq][j][k4]
__device__ __align__(16) float g_Dt[NB * DM * HID];   // [i][a][j]

__global__ void reorder_kernel(const float* __restrict__ We,
                               const float* __restrict__ Dw) {
    int idx = blockIdx.x * 256 + threadIdx.x;
    if (idx < DM * IN_DIM) {
        int j = idx / IN_DIM, k = idx - j * IN_DIM;
        g_Wq[(k >> 2) * (DM * 4) + j * 4 + (k & 3)] = We[idx];
    }
    if (idx < NB * DM * HID) {
        int i = idx / (DM * HID), r = idx % (DM * HID);
        int j = r / HID, a = r % HID;
        g_Dt[i * (DM * HID) + a * DM + j] = Dw[idx];
    }
}

__device__ __forceinline__ void fma2(unsigned long long& acc,
                                     unsigned long long a, unsigned long long b) {
    asm("fma.rn.f32x2 %0, %1, %2, %0;" : "+l"(acc) : "l"(a), "l"(b));
}

#define MB_INIT(addr, cnt) \
    asm volatile("mbarrier.init.shared.b64 [%0], %1;" :: "r"(addr), "r"(cnt) : "memory")
#define MB_EXPECT_TX(addr, bytes) \
    asm volatile("mbarrier.arrive.expect_tx.shared.b64 _, [%0], %1;" :: "r"(addr), "r"(bytes) : "memory")
#define MB_WAIT(addr, parity) do {                                                  \
    asm volatile("{\n\t.reg .pred P;\n"                                             \
        "WLP%=:\n\tmbarrier.try_wait.parity.acquire.cta.shared::cta.b64 P, [%0], %1, 0x989680;\n" \
        "\t@P bra WDN%=;\n\tbra WLP%=;\nWDN%=:\n\t}"                                \
        :: "r"(addr), "r"(parity) : "memory"); } while (0)
#define TMA_2D(dst, tmapp, cx, cy, mb)                                              \
    asm volatile("cp.async.bulk.tensor.2d.shared::cta.global.tile.mbarrier::complete_tx::bytes " \
        "[%0], [%1, {%2, %3}], [%4];"                                               \
        :: "r"(dst), "l"(tmapp), "r"(cx), "r"(cy), "r"(mb) : "memory")

__global__ __launch_bounds__(NTH, 2)
void bilinear_resnet_kernel(const __grid_constant__ CUtensorMap tmap,
                            const float* __restrict__ Lw,
                            const float* __restrict__ Rw,
                            const float* __restrict__ Wh,
                            float* __restrict__ out,
                            int batch)
{
    extern __shared__ float sm[];
    const int tid = threadIdx.x;
    const unsigned smbase = (unsigned)__cvta_generic_to_shared(sm);
    const unsigned mb0 = smbase + MBAR_F * 4;
    const unsigned mb1 = mb0 + 8;
    const int row0 = blockIdx.x * TROWS;

    // stage W into smem (coalesced from reordered global)
    {
        const float4* s = (const float4*)g_Wq;
        float4* d = (float4*)(sm + WOFF);
        for (int i = tid; i < WSZ / 4; i += NTH) d[i] = s[i];
    }
    if (tid == 0) { MB_INIT(mb0, 1); MB_INIT(mb1, 1); }
    __syncthreads();

    if (tid == 0) {
        MB_EXPECT_TX(mb0, XBUF * 4);
        TMA_2D(smbase, &tmap, 0, row0, mb0);
        MB_EXPECT_TX(mb1, XBUF * 4);
        TMA_2D(smbase + XBUF * 4, &tmap, KC, row0, mb1);
    }

    unsigned long long acc[RPT][DM];
    #pragma unroll
    for (int r = 0; r < RPT; r++)
        #pragma unroll
        for (int j = 0; j < DM; j++) acc[r][j] = 0ull;

    for (int c = 0; c < NCHUNK; c++) {
        MB_WAIT((c & 1) ? mb1 : mb0, (c >> 1) & 1);

        const float* xb = sm + (c & 1) * XBUF;
        const float* wb = sm + WOFF + c * (NKQ * DM * 4);
        #pragma unroll
        for (int kq = 0; kq < NKQ; kq++) {
            ulonglong2 xv0 = *(const ulonglong2*)(xb + tid * KC + kq * 4);
            ulonglong2 xv1 = *(const ulonglong2*)(xb + (tid + NTH) * KC + kq * 4);
            #pragma unroll
            for (int j = 0; j < DM; j++) {
                ulonglong2 wv = *(const ulonglong2*)(wb + kq * (DM * 4) + j * 4);
                fma2(acc[0][j], xv0.x, wv.x);
                fma2(acc[0][j], xv0.y, wv.y);
                fma2(acc[1][j], xv1.x, wv.x);
                fma2(acc[1][j], xv1.y, wv.y);
            }
        }
        __syncthreads();   // everyone done reading buf (c&1)
        if (c + 2 < NCHUNK && tid == 0) {
            unsigned mb = (c & 1) ? mb1 : mb0;
            MB_EXPECT_TX(mb, XBUF * 4);
            TMA_2D(smbase + (c & 1) * XBUF * 4, &tmap, (c + 2) * KC, row0, mb);
        }
    }

    // ---- phase 2: fully register-resident, weights via broadcast global loads ----
    const long long hbase = (long long)batch * NC;
    const long long hblk  = (long long)batch * HID;

    #pragma unroll
    for (int r = 0; r < RPT; r++) {
        float hx[DM];
        #pragma unroll
        for (int j = 0; j < DM; j++) {
            unsigned long long a = acc[r][j];
            hx[j] = __uint_as_float((unsigned)a) + __uint_as_float((unsigned)(a >> 32));
        }

        const long long grow = row0 + tid + r * NTH;

        #pragma unroll
        for (int ib = 0; ib < NB; ib++) {
            float h[HID];
            #pragma unroll
            for (int a = 0; a < HID; a++) {
                const float4* lp = (const float4*)(Lw + ib * (HID * DM) + a * DM);
                const float4* rp = (const float4*)(Rw + ib * (HID * DM) + a * DM);
                float su = 0.f, sv = 0.f;
                #pragma unroll
                for (int q = 0; q < 4; q++) {
                    float4 l4 = __ldg(lp + q), r4 = __ldg(rp + q);
                    su = fmaf(l4.x, hx[q*4+0], fmaf(l4.y, hx[q*4+1],
                         fmaf(l4.z, hx[q*4+2], fmaf(l4.w, hx[q*4+3], su))));
                    sv = fmaf(r4.x, hx[q*4+0], fmaf(r4.y, hx[q*4+1],
                         fmaf(r4.z, hx[q*4+2], fmaf(r4.w, hx[q*4+3], sv))));
                }
                h[a] = su * sv;
            }
            // store h (6 floats -> 3 x float2, 8B aligned since 6*grow even)
            {
                float* hp = out + hbase + (long long)ib * hblk + grow * HID;
                *(float2*)(hp + 0) = make_float2(h[0], h[1]);
                *(float2*)(hp + 2) = make_float2(h[2], h[3]);
                *(float2*)(hp + 4) = make_float2(h[4], h[5]);
            }
            #pragma unroll
            for (int a = 0; a < HID; a++) {
                const float4* dp = (const float4*)(g_Dt + ib * (DM * HID) + a * DM);
                #pragma unroll
                for (int q = 0; q < 4; q++) {
                    float4 d4 = dp[q];
                    hx[q*4+0] = fmaf(h[a], d4.x, hx[q*4+0]);
                    hx[q*4+1] = fmaf(h[a], d4.y, hx[q*4+1]);
                    hx[q*4+2] = fmaf(h[a], d4.z, hx[q*4+2]);
                    hx[q*4+3] = fmaf(h[a], d4.w, hx[q*4+3]);
                }
            }
        }

        float lg[NC];
        #pragma unroll
        for (int cc = 0; cc < NC; cc++) {
            const float4* wp = (const float4*)(Wh + cc * DM);
            float s = 0.f;
            #pragma unroll
            for (int q = 0; q < 4; q++) {
                float4 w4 = __ldg(wp + q);
                s = fmaf(w4.x, hx[q*4+0], fmaf(w4.y, hx[q*4+1],
                    fmaf(w4.z, hx[q*4+2], fmaf(w4.w, hx[q*4+3], s))));
            }
            lg[cc] = s;
        }
        float* op = out + grow * NC;   // 10 floats, 8B aligned (10*grow even)
        *(float2*)(op + 0) = make_float2(lg[0], lg[1]);
        *(float2*)(op + 2) = make_float2(lg[2], lg[3]);
        *(float2*)(op + 4) = make_float2(lg[4], lg[5]);
        *(float2*)(op + 6) = make_float2(lg[6], lg[7]);
        *(float2*)(op + 8) = make_float2(lg[8], lg[9]);
    }
}

typedef CUresult (*PFN_encodeTiled)(
    CUtensorMap*, CUtensorMapDataType, cuuint32_t, void*,
    const cuuint64_t*, const cuuint64_t*, const cuuint32_t*, const cuuint32_t*,
    CUtensorMapInterleave, CUtensorMapSwizzle, CUtensorMapL2promotion,
    CUtensorMapFloatOOBfill);

extern "C" void kernel_launch(void* const* d_in, const int* in_sizes, int n_in,
                              void* d_out, int out_size)
{
    const float* x  = (const float*)d_in[0];
    const float* We = (const float*)d_in[1];
    const float* Lw = (const float*)d_in[2];
    const float* Rw = (const float*)d_in[3];
    const float* Dw = (const float*)d_in[4];
    const float* Wh = (const float*)d_in[5];
    float* out = (float*)d_out;

    int batch = in_sizes[0] / IN_DIM;   // 65536
    int grid  = batch / TROWS;          // 256

    // Build tensor map for x: [IN_DIM, batch] float32, box [KC, TROWS]
    CUtensorMap tmap;
    {
        void* fp = nullptr;
        cudaDriverEntryPointQueryResult st;
        cudaGetDriverEntryPoint("cuTensorMapEncodeTiled", &fp,
                                cudaEnableDefault, &st);
        PFN_encodeTiled enc = (PFN_encodeTiled)fp;
        cuuint64_t dims[2]    = {IN_DIM, (cuuint64_t)batch};
        cuuint64_t strides[1] = {IN_DIM * sizeof(float)};
        cuuint32_t box[2]     = {KC, TROWS};
        cuuint32_t estr[2]    = {1, 1};
        enc(&tmap, CU_TENSOR_MAP_DATA_TYPE_FLOAT32, 2, (void*)x,
            dims, strides, box, estr,
            CU_TENSOR_MAP_INTERLEAVE_NONE, CU_TENSOR_MAP_SWIZZLE_NONE,
            CU_TENSOR_MAP_L2_PROMOTION_L2_128B, CU_TENSOR_MAP_FLOAT_OOB_FILL_NONE);
    }

    reorder_kernel<<<(DM * IN_DIM + 255) / 256, 256>>>(We, Dw);

    size_t smem = (size_t)SMEM_FLOATS * sizeof(float);   // ~105 KB
    cudaFuncSetAttribute(bilinear_resnet_kernel,
                         cudaFuncAttributeMaxDynamicSharedMemorySize, (int)smem);
    bilinear_resnet_kernel<<<grid, NTH, smem>>>(tmap, Lw, Rw, Wh, out, batch);
}